// round 7
// baseline (speedup 1.0000x reference)
#include <cuda_runtime.h>
#include <cstdint>

#define DIM 768
#define HEADS 12
#define HD 64
#define G 48
#define NTOK 2304
#define RANK 8
#define NKT 36      // 2304/64 k-tiles

// ---------------- scratch --------------------------------------------------
__device__ __align__(16) float g_x[NTOK*DIM];          // tf32-rounded x
__device__ __align__(16) float g_Wqkv[3*DIM*DIM];      // fused+transposed+rounded [n][k]
__device__ __align__(16) float g_Wp[DIM*DIM];          // transposed+rounded [n][k]
__device__ __align__(16) float g_q[HEADS*NTOK*HD];     // [h][m][c] tf32
__device__ __align__(16) float g_k[HEADS*NTOK*HD];     // [h][m][c] tf32
__device__ __align__(16) float g_v[HEADS*NTOK*HD];     // [h][c][m] TRANSPOSED tf32
__device__ __align__(16) float g_relh[HEADS*NTOK*G];
__device__ __align__(16) float g_relw[HEADS*NTOK*G];
__device__ __align__(16) float g_ao[NTOK*DIM];         // tf32-rounded

// ---------------- helpers ---------------------------------------------------
__device__ __forceinline__ float tf32r(float f) {
    unsigned u; asm("cvt.rna.tf32.f32 %0, %1;" : "=r"(u) : "f"(f));
    return __uint_as_float(u);
}
__device__ __forceinline__ void mma8(float* d,
                                     float a0, float a1, float a2, float a3,
                                     float b0, float b1) {
    unsigned ua0 = __float_as_uint(a0), ua1 = __float_as_uint(a1);
    unsigned ua2 = __float_as_uint(a2), ua3 = __float_as_uint(a3);
    unsigned ub0 = __float_as_uint(b0), ub1 = __float_as_uint(b1);
    asm volatile("mma.sync.aligned.m16n8k8.row.col.f32.tf32.tf32.f32 "
                 "{%0,%1,%2,%3},{%4,%5,%6,%7},{%8,%9},{%0,%1,%2,%3};"
                 : "+f"(d[0]), "+f"(d[1]), "+f"(d[2]), "+f"(d[3])
                 : "r"(ua0), "r"(ua1), "r"(ua2), "r"(ua3), "r"(ub0), "r"(ub1));
}
__device__ __forceinline__ void cpa16(uint32_t dst, const float* src) {
    asm volatile("cp.async.cg.shared.global [%0], [%1], 16;" :: "r"(dst), "l"(src));
}
#define CP_COMMIT() asm volatile("cp.async.commit_group;")
#define CP_WAIT(n)  asm volatile("cp.async.wait_group " #n ";")

// ---------------- kernel 0: round x to tf32 --------------------------------
__global__ __launch_bounds__(256) void round_x(const float* __restrict__ x) {
    int i = (blockIdx.x * 256 + threadIdx.x) * 4;
    float4 v = *(const float4*)(x + i);
    float4 o = make_float4(tf32r(v.x), tf32r(v.y), tf32r(v.z), tf32r(v.w));
    *(float4*)(g_x + i) = o;
}

// ---------------- kernel 1: fuse LoRA + transpose + round -------------------
__global__ __launch_bounds__(256) void fuse_wt(
    const float* __restrict__ Wq, const float* __restrict__ Aq, const float* __restrict__ Bq,
    const float* __restrict__ Wk, const float* __restrict__ Ak, const float* __restrict__ Bk,
    const float* __restrict__ Wv, const float* __restrict__ Av, const float* __restrict__ Bv,
    const float* __restrict__ Wp)
{
    __shared__ float tb[32][33];
    int z = blockIdx.z;
    const float *W, *A = nullptr, *B = nullptr;
    float* O;
    if (z == 0)      { W = Wq; A = Aq; B = Bq; O = g_Wqkv; }
    else if (z == 1) { W = Wk; A = Ak; B = Bk; O = g_Wqkv + DIM*DIM; }
    else if (z == 2) { W = Wv; A = Av; B = Bv; O = g_Wqkv + 2*DIM*DIM; }
    else             { W = Wp;                 O = g_Wp; }
    int kb = blockIdx.y * 32, nb = blockIdx.x * 32;
    int tx = threadIdx.x & 31, ty = threadIdx.x >> 5;
#pragma unroll
    for (int s = 0; s < 4; s++)
        tb[ty + 8 * s][tx] = W[(kb + ty + 8 * s) * DIM + nb + tx];
    __syncthreads();
#pragma unroll
    for (int s = 0; s < 4; s++) {
        int n = nb + ty + 8 * s;
        int k = kb + tx;
        float v = tb[tx][ty + 8 * s];
        if (z < 3) {
#pragma unroll
            for (int r = 0; r < RANK; r++)
                v += A[k * RANK + r] * B[r * DIM + n];
        }
        O[n * DIM + k] = tf32r(v);
    }
}

// ---------------- GEMM core (templated n-tile): 128m x (NJ*16)n, k=32 x2buf-
#define LDA 40
#define GBUFA (128*LDA)
template<int NJ>
__device__ __forceinline__ void gemm_body_t(const float* __restrict__ Ain,
                                            const float* __restrict__ Btn,
                                            float acc[2][NJ][4], float* sm)
{
    const int NROWS = NJ * 16;
    const int GBUFB = NROWS * LDA;
    int tid = threadIdx.x;
    int w = tid >> 5, l = tid & 31, g = l >> 2, t = l & 3;
    int wm = w >> 1, wn = w & 1;
    float* AS0 = sm;                 float* AS1 = AS0 + GBUFA;
    float* BS0 = AS1 + GBUFA;        float* BS1 = BS0 + GBUFB;
    uint32_t as0 = (uint32_t)__cvta_generic_to_shared(AS0);
    uint32_t as1 = (uint32_t)__cvta_generic_to_shared(AS1);
    uint32_t bs0 = (uint32_t)__cvta_generic_to_shared(BS0);
    uint32_t bs1 = (uint32_t)__cvta_generic_to_shared(BS1);

#pragma unroll
    for (int s = 0; s < 4; s++) {
        int id4 = tid + s * 256;
        int r = id4 >> 3, kc = (id4 & 7) * 4;
        cpa16(as0 + (r * LDA + kc) * 4, Ain + r * DIM + kc);
    }
#pragma unroll
    for (int s = 0; s < NJ / 2; s++) {
        int id4 = tid + s * 256;
        int r = id4 >> 3, kc = (id4 & 7) * 4;
        cpa16(bs0 + (r * LDA + kc) * 4, Btn + r * DIM + kc);
    }
    CP_COMMIT();

    for (int c = 0; c < 24; c++) {
        int buf = c & 1;
        if (c < 23) {
            uint32_t ad = buf ? as0 : as1;
            uint32_t bd = buf ? bs0 : bs1;
            int k0 = (c + 1) * 32;
#pragma unroll
            for (int s = 0; s < 4; s++) {
                int id4 = tid + s * 256;
                int r = id4 >> 3, kc = (id4 & 7) * 4;
                cpa16(ad + (r * LDA + kc) * 4, Ain + r * DIM + k0 + kc);
            }
#pragma unroll
            for (int s = 0; s < NJ / 2; s++) {
                int id4 = tid + s * 256;
                int r = id4 >> 3, kc = (id4 & 7) * 4;
                cpa16(bd + (r * LDA + kc) * 4, Btn + r * DIM + k0 + kc);
            }
            CP_COMMIT();
            CP_WAIT(1);
        } else {
            CP_WAIT(0);
        }
        __syncthreads();
        const float* As = buf ? AS1 : AS0;
        const float* Bs = buf ? BS1 : BS0;
#pragma unroll
        for (int ks = 0; ks < 4; ks++) {
            int kb = ks * 8 + 2 * t;      // k=t -> phys 2t, k=t+4 -> phys 2t+1
            float2 alo[2], ahi[2];
#pragma unroll
            for (int i = 0; i < 2; i++) {
                int r = wm * 32 + i * 16;
                alo[i] = *(const float2*)&As[(r + g) * LDA + kb];
                ahi[i] = *(const float2*)&As[(r + g + 8) * LDA + kb];
            }
#pragma unroll
            for (int j = 0; j < NJ; j++) {
                int n = wn * (NJ * 8) + j * 8;
                float2 b = *(const float2*)&Bs[(n + g) * LDA + kb];
                mma8(acc[0][j], alo[0].x, ahi[0].x, alo[0].y, ahi[0].y, b.x, b.y);
                mma8(acc[1][j], alo[1].x, ahi[1].x, alo[1].y, ahi[1].y, b.x, b.y);
            }
        }
        __syncthreads();
    }
}

// ---------------- kernel 2: fused QKV GEMM (128m x 64n tiles) --------------
__global__ __launch_bounds__(256, 2) void gemm_qkvf(
    const float* __restrict__ bq, const float* __restrict__ bk, const float* __restrict__ bv)
{
    extern __shared__ float sm[];
    int m0 = blockIdx.y * 128, n0 = blockIdx.x * 64;
    float acc[2][4][4];
#pragma unroll
    for (int i = 0; i < 2; i++)
#pragma unroll
        for (int j = 0; j < 4; j++)
#pragma unroll
            for (int e = 0; e < 4; e++) acc[i][j][e] = 0.f;
    gemm_body_t<4>(g_x + m0 * DIM, g_Wqkv + n0 * DIM, acc, sm);

    int z = n0 / DIM;
    int nb = n0 - z * DIM;
    const float* bias = (z == 0) ? bq : (z == 1) ? bk : bv;
    float* outp       = (z == 0) ? g_q : (z == 1) ? g_k : g_v;
    int tid = threadIdx.x;
    int w = tid >> 5, l = tid & 31, g = l >> 2, t = l & 3;
    int wm = w >> 1, wn = w & 1;
#pragma unroll
    for (int i = 0; i < 2; i++) {
        int r0 = m0 + wm * 32 + i * 16 + g;
#pragma unroll
        for (int j = 0; j < 4; j++) {
            int c = nb + wn * 32 + j * 8 + t * 2;
            int h = c >> 6, cc = c & 63;
            float e0 = tf32r(acc[i][j][0] + bias[c]);
            float e1 = tf32r(acc[i][j][1] + bias[c + 1]);
            float e2 = tf32r(acc[i][j][2] + bias[c]);
            float e3 = tf32r(acc[i][j][3] + bias[c + 1]);
            if (z == 2) {   // V: transposed layout [h][c][m]
                float* vb = outp + h * (NTOK * HD);
                vb[cc * NTOK + r0]           = e0;
                vb[(cc + 1) * NTOK + r0]     = e1;
                vb[cc * NTOK + r0 + 8]       = e2;
                vb[(cc + 1) * NTOK + r0 + 8] = e3;
            } else {
                *(float2*)&outp[h * (NTOK * HD) + r0 * HD + cc] = make_float2(e0, e1);
                *(float2*)&outp[h * (NTOK * HD) + (r0 + 8) * HD + cc] = make_float2(e2, e3);
            }
        }
    }
}

// ---------------- kernel 5: output projection (128m x 64n tiles) ------------
__global__ __launch_bounds__(256, 2) void gemm_projf(
    const float* __restrict__ bp, float* __restrict__ out)
{
    extern __shared__ float sm[];
    int m0 = blockIdx.y * 128, n0 = blockIdx.x * 64;
    float acc[2][4][4];
#pragma unroll
    for (int i = 0; i < 2; i++)
#pragma unroll
        for (int j = 0; j < 4; j++)
#pragma unroll
            for (int e = 0; e < 4; e++) acc[i][j][e] = 0.f;
    gemm_body_t<4>(g_ao + m0 * DIM, g_Wp + n0 * DIM, acc, sm);

    int tid = threadIdx.x;
    int w = tid >> 5, l = tid & 31, g = l >> 2, t = l & 3;
    int wm = w >> 1, wn = w & 1;
#pragma unroll
    for (int i = 0; i < 2; i++) {
        int r0 = m0 + wm * 32 + i * 16 + g;
#pragma unroll
        for (int j = 0; j < 4; j++) {
            int c = n0 + wn * 32 + j * 8 + t * 2;
            float2 v0 = make_float2(acc[i][j][0] + bp[c], acc[i][j][1] + bp[c + 1]);
            float2 v1 = make_float2(acc[i][j][2] + bp[c], acc[i][j][3] + bp[c + 1]);
            *(float2*)&out[r0 * DIM + c] = v0;
            *(float2*)&out[(r0 + 8) * DIM + c] = v1;
        }
    }
}

// ---------------- kernel 3: rel-pos tables via tensor cores ----------------
#define RLD 68
__global__ __launch_bounds__(192) void rel_mma(
    const float* __restrict__ rph, const float* __restrict__ rpw)
{
    __shared__ float qs[48 * RLD];
    __shared__ float rp[48 * RLD];
    int head = blockIdx.x, p = blockIdx.y, z = blockIdx.z;
    int tid = threadIdx.x;
    const float* qhead = g_q + head * (NTOK * HD);
    const float* rpsrc = (z == 0) ? rph : rpw;

#pragma unroll
    for (int s = 0; s < 4; s++) {
        int id4 = tid + s * 192;
        int r = id4 >> 4, c = (id4 & 15) * 4;
        int n = (z == 0) ? (p * G + r) : (r * G + p);
        *(float4*)&qs[r * RLD + c] = *(const float4*)(qhead + n * HD + c);
        float4 rv = *(const float4*)(rpsrc + (p + r) * HD + c);
        float4 ro = make_float4(tf32r(rv.x), tf32r(rv.y), tf32r(rv.z), tf32r(rv.w));
        *(float4*)&rp[r * RLD + c] = ro;
    }
    __syncthreads();

    int w = tid >> 5, l = tid & 31, g = l >> 2, t = l & 3;
    float acc[3][4];
#pragma unroll
    for (int i = 0; i < 3; i++)
#pragma unroll
        for (int e = 0; e < 4; e++) acc[i][e] = 0.f;

#pragma unroll
    for (int ks = 0; ks < 8; ks++) {
        int kb = ks * 8;
        int brow = 47 - (w * 8 + g);
        float b0 = rp[brow * RLD + kb + t];
        float b1 = rp[brow * RLD + kb + t + 4];
#pragma unroll
        for (int i = 0; i < 3; i++) {
            int r = i * 16;
            float a0 = qs[(r + g) * RLD + kb + t];
            float a1 = qs[(r + g + 8) * RLD + kb + t];
            float a2 = qs[(r + g) * RLD + kb + t + 4];
            float a3 = qs[(r + g + 8) * RLD + kb + t + 4];
            mma8(acc[i], a0, a1, a2, a3, b0, b1);
        }
    }

    float* dst = (z == 0) ? g_relh : g_relw;
    int j = w * 8 + t * 2;
#pragma unroll
    for (int i = 0; i < 3; i++) {
        int r0 = i * 16 + g;
        int n0 = (z == 0) ? (p * G + r0)     : (r0 * G + p);
        int n1 = (z == 0) ? (p * G + r0 + 8) : ((r0 + 8) * G + p);
        *(float2*)&dst[(head * NTOK + n0) * G + j] = make_float2(acc[i][0], acc[i][1]);
        *(float2*)&dst[(head * NTOK + n1) * G + j] = make_float2(acc[i][2], acc[i][3]);
    }
}

// ---------------- kernel 4: flash attention (all-register P, 1 sync/iter) --
#define LKS 72
#define LVT 72
__global__ __launch_bounds__(128, 3) void flash4()
{
    extern __shared__ float sm[];
    float* Kb[2] = { sm,              sm + 64 * LKS };
    float* Vb[2] = { sm + 2*64*LKS,   sm + 2*64*LKS + 64 * LVT };
    uint32_t kba[2] = { (uint32_t)__cvta_generic_to_shared(Kb[0]),
                        (uint32_t)__cvta_generic_to_shared(Kb[1]) };
    uint32_t vba[2] = { (uint32_t)__cvta_generic_to_shared(Vb[0]),
                        (uint32_t)__cvta_generic_to_shared(Vb[1]) };

    int tile = blockIdx.x, head = blockIdx.y;
    int tid = threadIdx.x, w = tid >> 5, l = tid & 31, g = l >> 2, t = l & 3;
    const float* qb    = g_q + head * (NTOK * HD) + tile * 64 * HD;
    const float* kbase = g_k + head * (NTOK * HD);
    const float* vtb   = g_v + head * (NTOK * HD);   // [c][m]

    int pr = w * 16;
    // Q fragments straight from global (q is tf32; x0.125 exact in tf32)
    float qf[8][4];
#pragma unroll
    for (int ks = 0; ks < 8; ks++) {
        float2 lo = *(const float2*)(qb + (pr + g) * HD + ks * 8 + 2 * t);
        float2 hi = *(const float2*)(qb + (pr + g + 8) * HD + ks * 8 + 2 * t);
        qf[ks][0] = lo.x * 0.125f; qf[ks][1] = hi.x * 0.125f;
        qf[ks][2] = lo.y * 0.125f; qf[ks][3] = hi.y * 0.125f;
    }

    // issue K(0) + V(0) as one group
#pragma unroll
    for (int s = 0; s < 8; s++) {
        int id4 = tid + s * 128;
        int r = id4 >> 4, c4 = (id4 & 15) * 4;
        cpa16(kba[0] + (r * LKS + c4) * 4, kbase + id4 * 4);
        cpa16(vba[0] + (r * LVT + c4) * 4, vtb + r * NTOK + c4);
    }
    CP_COMMIT();

    int rg0 = tile * 64 + pr + g;
    const float* rhb = g_relh + head * NTOK * G;
    const float* rwb = g_relw + head * NTOK * G;

    float o[8][4];
#pragma unroll
    for (int j = 0; j < 8; j++)
#pragma unroll
        for (int e = 0; e < 4; e++) o[j][e] = 0.f;
    float m0v = -1e30f, m1v = -1e30f, l0 = 0.f, l1 = 0.f;

    for (int kt = 0; kt < NKT; kt++) {
        CP_WAIT(0);          // group kt complete (copied during compute kt-1)
        __syncthreads();     // visibility + all threads done reading kt-1 buffers

        // issue K(kt+1)+V(kt+1) — overlaps with compute(kt)
        if (kt + 1 < NKT) {
            int nb = (kt + 1) & 1;
            const float* ksrc = kbase + (kt + 1) * 64 * HD;
            const float* vsrc = vtb + (kt + 1) * 64;
#pragma unroll
            for (int s = 0; s < 8; s++) {
                int id4 = tid + s * 128;
                int r = id4 >> 4, c4 = (id4 & 15) * 4;
                cpa16(kba[nb] + (r * LKS + c4) * 4, ksrc + id4 * 4);
                cpa16(vba[nb] + (r * LVT + c4) * 4, vsrc + r * NTOK + c4);
            }
            CP_COMMIT();
        }

        const float* Ks = Kb[kt & 1];
        const float* Vt = Vb[kt & 1];

        // S = Q K^T
        float s4[8][4];
#pragma unroll
        for (int j = 0; j < 8; j++)
#pragma unroll
            for (int e = 0; e < 4; e++) s4[j][e] = 0.f;
#pragma unroll
        for (int ks = 0; ks < 8; ks++) {
            int kb2 = ks * 8 + 2 * t;
#pragma unroll
            for (int j = 0; j < 8; j++) {
                float2 b = *(const float2*)&Ks[(j * 8 + g) * LKS + kb2];
                mma8(s4[j], qf[ks][0], qf[ks][1], qf[ks][2], qf[ks][3], b.x, b.y);
            }
        }

        // decomposed rel-pos bias
        int colbase = kt * 64;
        int khA = colbase / G;
        int khB = (colbase + 63) / G;
        float rhA0 = rhb[rg0 * G + khA],       rhB0 = rhb[rg0 * G + khB];
        float rhA1 = rhb[(rg0 + 8) * G + khA], rhB1 = rhb[(rg0 + 8) * G + khB];
#pragma unroll
        for (int j = 0; j < 8; j++) {
            int c0 = colbase + j * 8 + t * 2;
            int c1 = c0 + 1;
            int kh0 = c0 / G, kw0 = c0 - kh0 * G;
            int kh1 = c1 / G, kw1 = c1 - kh1 * G;
            s4[j][0] += ((kh0 == khA) ? rhA0 : rhB0) + rwb[rg0 * G + kw0];
            s4[j][1] += ((kh1 == khA) ? rhA0 : rhB0) + rwb[rg0 * G + kw1];
            s4[j][2] += ((kh0 == khA) ? rhA1 : rhB1) + rwb[(rg0 + 8) * G + kw0];
            s4[j][3] += ((kh1 == khA) ? rhA1 : rhB1) + rwb[(rg0 + 8) * G + kw1];
        }

        // online softmax (registers)
        float mx0 = -1e30f, mx1 = -1e30f;
#pragma unroll
        for (int j = 0; j < 8; j++) {
            mx0 = fmaxf(mx0, fmaxf(s4[j][0], s4[j][1]));
            mx1 = fmaxf(mx1, fmaxf(s4[j][2], s4[j][3]));
        }
        mx0 = fmaxf(mx0, __shfl_xor_sync(0xffffffffu, mx0, 1));
        mx0 = fmaxf(mx0, __shfl_xor_sync(0xffffffffu, mx0, 2));
        mx1 = fmaxf(mx1, __shfl_xor_sync(0xffffffffu, mx1, 1));
        mx1 = fmaxf(mx1, __shfl_xor_sync(0xffffffffu, mx1, 2));
        float mn0 = fmaxf(m0v, mx0), mn1 = fmaxf(m1v, mx1);
        float sum0 = 0.f, sum1 = 0.f;
#pragma unroll
        for (int j = 0; j < 8; j++) {
            s4[j][0] = __expf(s4[j][0] - mn0);
            s4[j][1] = __expf(s4[j][1] - mn0);
            s4[j][2] = __expf(s4[j][2] - mn1);
            s4[j][3] = __expf(s4[j][3] - mn1);
            sum0 += s4[j][0] + s4[j][1];
            sum1 += s4[j][2] + s4[j][3];
        }
        sum0 += __shfl_xor_sync(0xffffffffu, sum0, 1);
        sum0 += __shfl_xor_sync(0xffffffffu, sum0, 2);
        sum1 += __shfl_xor_sync(0xffffffffu, sum1, 1);
        sum1 += __shfl_xor_sync(0xffffffffu, sum1, 2);
        float al0 = __expf(m0v - mn0), al1 = __expf(m1v - mn1);
        l0 = l0 * al0 + sum0;  l1 = l1 * al1 + sum1;
        m0v = mn0;  m1v = mn1;
#pragma unroll
        for (int j = 0; j < 8; j++) {
            o[j][0] *= al0; o[j][1] *= al0;
            o[j][2] *= al1; o[j][3] *= al1;
            // round P for the tf32 mma
            s4[j][0] = tf32r(s4[j][0]); s4[j][1] = tf32r(s4[j][1]);
            s4[j][2] = tf32r(s4[j][2]); s4[j][3] = tf32r(s4[j][3]);
        }

        // O += P V : A-frag of PV == C-frag of S (d0,d2,d1,d3) — registers only
#pragma unroll
        for (int ms = 0; ms < 8; ms++) {
            int mb = ms * 8 + 2 * t;
#pragma unroll
            for (int j = 0; j < 8; j++) {
                float2 b = *(const float2*)&Vt[(j * 8 + g) * LVT + mb];
                mma8(o[j], s4[ms][0], s4[ms][2], s4[ms][1], s4[ms][3], b.x, b.y);
            }
        }
    }

    // epilogue (tf32-rounded for the projection GEMM)
    float inv0 = 1.f / l0, inv1 = 1.f / l1;
    int nq0 = tile * 64 + pr + g;
#pragma unroll
    for (int j = 0; j < 8; j++) {
        int c = head * HD + j * 8 + t * 2;
        float2 v0 = make_float2(tf32r(o[j][0] * inv0), tf32r(o[j][1] * inv0));
        float2 v1 = make_float2(tf32r(o[j][2] * inv1), tf32r(o[j][3] * inv1));
        *(float2*)&g_ao[nq0 * DIM + c] = v0;
        *(float2*)&g_ao[(nq0 + 8) * DIM + c] = v1;
    }
}

// ---------------- launch ----------------------------------------------------
extern "C" void kernel_launch(void* const* d_in, const int* in_sizes, int n_in,
                              void* d_out, int out_size)
{
    const float* x   = (const float*)d_in[0];
    const float* Wq  = (const float*)d_in[1];
    const float* bq  = (const float*)d_in[2];
    const float* Wk  = (const float*)d_in[3];
    const float* bk  = (const float*)d_in[4];
    const float* Wv  = (const float*)d_in[5];
    const float* bv  = (const float*)d_in[6];
    const float* Wp  = (const float*)d_in[7];
    const float* bp  = (const float*)d_in[8];
    const float* rph = (const float*)d_in[9];
    const float* rpw = (const float*)d_in[10];
    const float* Aq  = (const float*)d_in[11];
    const float* Bq  = (const float*)d_in[12];
    const float* Ak  = (const float*)d_in[13];
    const float* Bk  = (const float*)d_in[14];
    const float* Av  = (const float*)d_in[15];
    const float* Bv  = (const float*)d_in[16];
    float* out = (float*)d_out;

    const int gemm_smem  = (2 * GBUFA + 2 * 64 * LDA) * (int)sizeof(float);
    const int flash_smem = (2 * 64 * LKS + 2 * 64 * LVT) * (int)sizeof(float);  // 73728
    cudaFuncSetAttribute(gemm_qkvf, cudaFuncAttributeMaxDynamicSharedMemorySize, gemm_smem);
    cudaFuncSetAttribute(gemm_projf, cudaFuncAttributeMaxDynamicSharedMemorySize, gemm_smem);
    cudaFuncSetAttribute(flash4, cudaFuncAttributeMaxDynamicSharedMemorySize, flash_smem);

    round_x<<<NTOK * DIM / 1024, 256>>>(x);
    fuse_wt<<<dim3(24, 24, 4), 256>>>(Wq, Aq, Bq, Wk, Ak, Bk, Wv, Av, Bv, Wp);
    gemm_qkvf<<<dim3(36, 18), 256, gemm_smem>>>(bq, bk, bv);
    rel_mma<<<dim3(HEADS, G, 2), 192>>>(rph, rpw);
    flash4<<<dim3(NTOK / 64, HEADS), 128, flash_smem>>>();
    gemm_projf<<<dim3(12, 18), 256, gemm_smem>>>(bp, out);
}